// round 1
// baseline (speedup 1.0000x reference)
#include <cuda_runtime.h>

// ReNet layer: vertical bidirectional LSTM sweep over 2x2x3 patches, then
// horizontal bidirectional LSTM sweep. Exact fp32 math (fma.rn.f32x2 packed).
//
// Phase kernel: each CTA owns 32 sequences of one direction. Combined weight
// matrix [K][256] (K = DIN+64) lives in smem; per-seq vector xh[K] (input ++ h)
// lives in smem; c-state in registers. 128 threads: 4 seq-groups x 32 col-groups,
// per-thread tile = 8 seqs x (2 hid x 4 gates), FFMA2-packed over the hid pair.

#define HIDN 64
#define NGC  256      // 4*HID gate columns
#define BN   16
#define SJ   128      // J == I == 128 patches
#define NSEQ 32       // sequences per CTA
#define NTHR 128

typedef unsigned long long ull;

__device__ float g_v[BN * SJ * SJ * 2 * HIDN];   // vertical output [B][J][I][128], 134 MB

__device__ __forceinline__ ull pack2(float lo, float hi) {
    ull r; asm("mov.b64 %0, {%1, %2};" : "=l"(r) : "f"(lo), "f"(hi)); return r;
}
__device__ __forceinline__ void unpack2(ull v, float& lo, float& hi) {
    asm("mov.b64 {%0, %1}, %2;" : "=f"(lo), "=f"(hi) : "l"(v));
}
__device__ __forceinline__ void ffma2(ull& d, ull a, ull b) {
    asm("fma.rn.f32x2 %0, %1, %2, %0;" : "+l"(d) : "l"(a), "l"(b));
}
__device__ __forceinline__ float sigf(float x)   { return 1.0f / (1.0f + __expf(-x)); }
__device__ __forceinline__ float mytanh(float x) { return 1.0f - 2.0f / (__expf(2.0f * x) + 1.0f); }

template <int DIN>
__global__ void __launch_bounds__(NTHR, 1)
renet_pass(const float* __restrict__ W0, const float* __restrict__ U0, const float* __restrict__ b0,
           const float* __restrict__ W1, const float* __restrict__ U1, const float* __restrict__ b1,
           const float* __restrict__ src, float* __restrict__ dst)
{
    constexpr int K = DIN + HIDN;
    extern __shared__ float sm[];
    float* sWU = sm;                   // [K][NGC]   combined W;U
    float* sXH = sm + K * NGC;         // [NSEQ][K]  per-seq (x_t ++ h)
    float* sB  = sXH + NSEQ * K;       // [NGC]

    const int dir = blockIdx.x >> 6;          // 0: forward scan, 1: reversed input
    const int s0  = (blockIdx.x & 63) * NSEQ; // first sequence of this CTA
    const int tid = threadIdx.x;
    const int cg  = tid & 31;                 // column group: hid pair h0 = 2*cg
    const int sg  = tid >> 5;                 // seq group (warp): 8 seqs each
    const int h0  = 2 * cg;

    const float* W  = dir ? W1 : W0;
    const float* U  = dir ? U1 : U0;
    const float* bb = dir ? b1 : b0;

    for (int idx = tid; idx < DIN * NGC; idx += NTHR) sWU[idx] = W[idx];
    for (int idx = tid; idx < HIDN * NGC; idx += NTHR) sWU[DIN * NGC + idx] = U[idx];
    for (int idx = tid; idx < NGC; idx += NTHR) sB[idx] = bb[idx];
    for (int idx = tid; idx < NSEQ * HIDN; idx += NTHR) {
        int s = idx >> 6, h = idx & 63;
        sXH[s * K + DIN + h] = 0.0f;           // h_0 = 0
    }
    __syncthreads();

    ull biasr[4];
#pragma unroll
    for (int g = 0; g < 4; g++) biasr[g] = *(const ull*)&sB[g * HIDN + h0];

    float cst[16];                             // c-state: 8 seqs x 2 hid
#pragma unroll
    for (int p = 0; p < 16; p++) cst[p] = 0.0f;

    for (int t = 0; t < SJ; t++) {
        // ---- stage x_t into sXH[s][0..DIN)
        if (DIN == 12) {
            const int jin = dir ? (SJ - 1 - t) : t;
#pragma unroll
            for (int r = 0; r < 3; r++) {
                int e = tid + NTHR * r;        // 384 = 32 seq * 12
                int s = e / 12, d = e - s * 12;
                int q = s0 + s;
                int b = q >> 7, i = q & 127;
                int pr = d / 6, rm = d - pr * 6;
                int pc = rm / 3, ch = rm - pc * 3;
                sXH[s * K + d] =
                    src[((b * 256 + (2 * jin + pr)) * 256 + (2 * i + pc)) * 3 + ch];
            }
        } else {
            const int iin = dir ? (SJ - 1 - t) : t;
#pragma unroll
            for (int r = 0; r < 8; r++) {
                int idx = tid + NTHR * r;      // 1024 = 32 seq * 32 float4
                int s = idx >> 5, f4 = idx & 31;
                int q = s0 + s;
                int b = q >> 7, j = q & 127;
                float4 v4 = *(const float4*)
                    &src[((size_t)((b * 128 + j) * 128 + iin)) * 128 + f4 * 4];
                *(float4*)&sXH[s * K + f4 * 4] = v4;
            }
        }
        __syncthreads();   // x_t staged; h from step t-1 visible

        // ---- Z[s][c] = bias + (x ++ h) @ (W ;; U)
        ull acc[8][4];
#pragma unroll
        for (int m = 0; m < 8; m++)
#pragma unroll
            for (int g = 0; g < 4; g++) acc[m][g] = biasr[g];

        const float* xbase = sXH + (sg * 8) * K;
#pragma unroll 2
        for (int k = 0; k < K; k++) {
            const float* wr = sWU + k * NGC + h0;
            ull u0 = *(const ull*)(wr);
            ull u1 = *(const ull*)(wr + 64);
            ull u2 = *(const ull*)(wr + 128);
            ull u3 = *(const ull*)(wr + 192);
#pragma unroll
            for (int m = 0; m < 8; m++) {
                float a = xbase[m * K + k];    // broadcast within warp
                ull a2 = pack2(a, a);
                ffma2(acc[m][0], a2, u0);
                ffma2(acc[m][1], a2, u1);
                ffma2(acc[m][2], a2, u2);
                ffma2(acc[m][3], a2, u3);
            }
        }
        __syncthreads();   // everyone done reading sXH before h overwrite

        // ---- gates, state update, h write-back + global store
#pragma unroll
        for (int m = 0; m < 8; m++) {
            float zi0, zi1, zf0, zf1, zg0, zg1, zo0, zo1;
            unpack2(acc[m][0], zi0, zi1);
            unpack2(acc[m][1], zf0, zf1);
            unpack2(acc[m][2], zg0, zg1);
            unpack2(acc[m][3], zo0, zo1);
            float c0 = cst[2 * m], c1 = cst[2 * m + 1];
            c0 = sigf(zf0) * c0 + sigf(zi0) * mytanh(zg0);
            c1 = sigf(zf1) * c1 + sigf(zi1) * mytanh(zg1);
            cst[2 * m] = c0; cst[2 * m + 1] = c1;
            float hh0 = sigf(zo0) * mytanh(c0);
            float hh1 = sigf(zo1) * mytanh(c1);

            int s = sg * 8 + m;
            *(float2*)&sXH[s * K + DIN + h0] = make_float2(hh0, hh1);

            int q = s0 + s;
            int b = q >> 7, w = q & 127;
            // vertical:   v[b][t][w][dir*64 + h]   (seq index w = column i)
            // horizontal: out[b][w][t][dir*64 + h] (seq index w = row j)
            int row = (DIN == 12) ? t : w;
            int col = (DIN == 12) ? w : t;
            size_t off = ((size_t)((b * 128 + row) * 128 + col)) * 128 + dir * 64 + h0;
            *(float2*)&dst[off] = make_float2(hh0, hh1);
        }
        // note: no sync needed here; next-iter x staging writes a disjoint smem
        // region, and the next __syncthreads() orders h writes vs. GEMM reads.
    }
}

extern "C" void kernel_launch(void* const* d_in, const int* in_sizes, int n_in,
                              void* d_out, int out_size)
{
    const float* inputs = (const float*)d_in[0];
    const float* W_ud = (const float*)d_in[1];
    const float* U_ud = (const float*)d_in[2];
    const float* b_ud = (const float*)d_in[3];
    const float* W_du = (const float*)d_in[4];
    const float* U_du = (const float*)d_in[5];
    const float* b_du = (const float*)d_in[6];
    const float* W_lr = (const float*)d_in[7];
    const float* U_lr = (const float*)d_in[8];
    const float* b_lr = (const float*)d_in[9];
    const float* W_rl = (const float*)d_in[10];
    const float* U_rl = (const float*)d_in[11];
    const float* b_rl = (const float*)d_in[12];

    float* vbuf = nullptr;
    cudaGetSymbolAddress((void**)&vbuf, g_v);

    constexpr int K1 = 12 + HIDN;    // 76
    constexpr int K2 = 128 + HIDN;   // 192
    size_t smem1 = (size_t)(K1 * NGC + NSEQ * K1 + NGC) * sizeof(float);  //  88,576 B
    size_t smem2 = (size_t)(K2 * NGC + NSEQ * K2 + NGC) * sizeof(float);  // 222,208 B

    cudaFuncSetAttribute(renet_pass<12>,  cudaFuncAttributeMaxDynamicSharedMemorySize, (int)smem1);
    cudaFuncSetAttribute(renet_pass<128>, cudaFuncAttributeMaxDynamicSharedMemorySize, (int)smem2);

    // vertical sweep: 2 dirs x 2048 seqs (seq = b*128 + i), writes g_v[B][J][I][128]
    renet_pass<12><<<128, NTHR, smem1>>>(W_ud, U_ud, b_ud, W_du, U_du, b_du,
                                         inputs, vbuf);
    // horizontal sweep: 2 dirs x 2048 seqs (seq = b*128 + j), writes out[B][J][I][128]
    renet_pass<128><<<128, NTHR, smem2>>>(W_lr, U_lr, b_lr, W_rl, U_rl, b_rl,
                                          vbuf, (float*)d_out);
}